// round 8
// baseline (speedup 1.0000x reference)
#include <cuda_runtime.h>
#include <cuda_bf16.h>
#include <stdint.h>

#define NN   2048
#define DD   512
#define CC   128
#define BB   4096
#define TOPK 10
#define KSEL 12

// ---------------- device scratch ----------------
__device__ __align__(16) __nv_bfloat16 g_hi[(size_t)BB * DD];   // 4 MB
__device__ __align__(16) unsigned short g_pdq[(size_t)BB * BB]; // 32 MB quantized d2
__device__ __align__(16) float g_probs[(size_t)BB * CC];
__device__ float g_sq[BB];
__device__ float g_partial[BB];

// ---------------- helpers ----------------
__device__ __forceinline__ uint32_t smem_u32(const void* p) {
    uint32_t a;
    asm("{ .reg .u64 t; cvta.to.shared.u64 t, %1; cvt.u32.u64 %0, t; }"
        : "=r"(a) : "l"(p));
    return a;
}
__device__ __forceinline__ void ldsm4(uint32_t& r0, uint32_t& r1, uint32_t& r2,
                                      uint32_t& r3, uint32_t addr) {
    asm volatile("ldmatrix.sync.aligned.m8n8.x4.shared.b16 {%0,%1,%2,%3}, [%4];"
                 : "=r"(r0), "=r"(r1), "=r"(r2), "=r"(r3) : "r"(addr));
}
__device__ __forceinline__ void mma16816(float* c, const uint32_t* a,
                                         uint32_t b0, uint32_t b1) {
    asm volatile(
        "mma.sync.aligned.m16n8k16.row.col.f32.bf16.bf16.f32 "
        "{%0,%1,%2,%3}, {%4,%5,%6,%7}, {%8,%9}, {%0,%1,%2,%3};"
        : "+f"(c[0]), "+f"(c[1]), "+f"(c[2]), "+f"(c[3])
        : "r"(a[0]), "r"(a[1]), "r"(a[2]), "r"(a[3]), "r"(b0), "r"(b1));
}
#define CP_ASYNC16(dst, src) \
    asm volatile("cp.async.cg.shared.global [%0], [%1], 16;" :: "r"(dst), "l"(src))
#define CP_COMMIT()  asm volatile("cp.async.commit_group;" ::: "memory")
#define CP_WAIT0()   asm volatile("cp.async.wait_group 0;" ::: "memory")

__device__ __forceinline__ unsigned short quant16(float d2) {
    int q = (int)(d2 * 16.f);
    q = max(0, min(q, 65534));
    return (unsigned short)q;
}

// ---------------- pack: bf16 hi + probs copy ----------------
__global__ void pack_kernel(const float* __restrict__ zi, const float* __restrict__ zj,
                            const float* __restrict__ pi, const float* __restrict__ pj) {
    const int total_f4 = NN * DD / 4;
    const int total_p4 = NN * CC / 4;
    for (int i4 = blockIdx.x * blockDim.x + threadIdx.x; i4 < total_f4;
         i4 += gridDim.x * blockDim.x) {
        float4 a = ((const float4*)zi)[i4];
        float4 b = ((const float4*)zj)[i4];
        __nv_bfloat162* hi2 = (__nv_bfloat162*)g_hi;
        hi2[2 * i4]     = __nv_bfloat162{__float2bfloat16(a.x), __float2bfloat16(a.y)};
        hi2[2 * i4 + 1] = __nv_bfloat162{__float2bfloat16(a.z), __float2bfloat16(a.w)};
        const int off = total_f4;
        hi2[2 * (off + i4)]     = __nv_bfloat162{__float2bfloat16(b.x), __float2bfloat16(b.y)};
        hi2[2 * (off + i4) + 1] = __nv_bfloat162{__float2bfloat16(b.z), __float2bfloat16(b.w)};
        if (i4 < total_p4) {
            ((float4*)g_probs)[i4]            = ((const float4*)pi)[i4];
            ((float4*)g_probs)[total_p4 + i4] = ((const float4*)pj)[i4];
        }
    }
}

// ---------------- row squared norms (fp32 originals) ----------------
__global__ void sqnorm_kernel(const float* __restrict__ zi, const float* __restrict__ zj) {
    int warp = (blockIdx.x * blockDim.x + threadIdx.x) >> 5;
    int lane = threadIdx.x & 31;
    if (warp >= BB) return;
    const float* row = (warp < NN) ? (zi + (size_t)warp * DD)
                                   : (zj + (size_t)(warp - NN) * DD);
    float s = 0.f;
    #pragma unroll
    for (int q = 0; q < 4; q++) {
        float4 v = *(const float4*)(row + (q * 32 + lane) * 4);
        s += v.x * v.x + v.y * v.y + v.z * v.z + v.w * v.w;
    }
    #pragma unroll
    for (int off = 16; off > 0; off >>= 1)
        s += __shfl_down_sync(0xffffffffu, s, off);
    if (lane == 0) g_sq[warp] = s;
}

// ---------------- 1-product bf16 GEMM -> quantized d2 ----------------
#define BUF_B   10240
#define STAGE_B (2 * BUF_B)
#define DSMEM_B 67072

extern __shared__ char dynsm[];

__global__ void __launch_bounds__(256, 1) dist_gemm_mma() {
    int t = blockIdx.x;
    int bi = 0;
    while (t >= 32 - bi) { t -= 32 - bi; bi++; }
    const int bj = bi + t;

    const int tid  = threadIdx.x;
    const int wid  = tid >> 5;
    const int lane = tid & 31;
    const int wm   = (wid >> 2) * 64;
    const int wn   = (wid & 3) * 32;

    const uint32_t sbase = smem_u32(dynsm);

    const __nv_bfloat16* src[4];
    uint32_t dst[4];
    #pragma unroll
    for (int it = 0; it < 4; it++) {
        const int cid = it * 256 + tid;
        const int b   = cid >> 9;
        const int w   = cid & 511;
        const int row = w >> 2;
        const int seg = w & 3;
        const int grow = ((b == 0) ? bi : bj) * 128 + row;
        src[it] = g_hi + (size_t)grow * DD + seg * 8;
        dst[it] = sbase + b * BUF_B + row * 80 + seg * 16;
    }

    float acc[4][4][4];
    #pragma unroll
    for (int fm = 0; fm < 4; fm++)
        #pragma unroll
        for (int fn = 0; fn < 4; fn++)
            #pragma unroll
            for (int e = 0; e < 4; e++) acc[fm][fn][e] = 0.f;

    #pragma unroll
    for (int it = 0; it < 4; it++) CP_ASYNC16(dst[it], src[it]);
    CP_COMMIT();

    for (int ch = 0; ch < 16; ch++) {
        CP_WAIT0();
        __syncthreads();
        if (ch < 15) {
            const uint32_t soff = ((ch + 1) & 1) * STAGE_B;
            #pragma unroll
            for (int it = 0; it < 4; it++)
                CP_ASYNC16(dst[it] + soff, src[it] + (ch + 1) * 32);
            CP_COMMIT();
        }
        const uint32_t stg = sbase + (ch & 1) * STAGE_B;

        #pragma unroll
        for (int kst = 0; kst < 2; kst++) {
            const uint32_t ko = kst * 32 + (lane >> 4) * 16;
            uint32_t ahi[4][4];
            #pragma unroll
            for (int fm = 0; fm < 4; fm++) {
                const uint32_t ra = (wm + fm * 16 + (lane & 15)) * 80 + ko;
                ldsm4(ahi[fm][0], ahi[fm][1], ahi[fm][2], ahi[fm][3], stg + ra);
            }
            uint32_t bh[2][4];
            #pragma unroll
            for (int fp = 0; fp < 2; fp++) {
                const uint32_t rb = (wn + fp * 16 + (lane & 15)) * 80 + ko;
                ldsm4(bh[fp][0], bh[fp][1], bh[fp][2], bh[fp][3],
                      stg + BUF_B + rb);
            }
            #pragma unroll
            for (int fm = 0; fm < 4; fm++)
                #pragma unroll
                for (int fn = 0; fn < 4; fn++) {
                    const int fp = fn >> 1, s = fn & 1;
                    mma16816(acc[fm][fn], ahi[fm], bh[fp][s], bh[fp][s + 2]);
                }
        }
        __syncthreads();
    }

    // epilogue: dots -> smem -> quantized d2 stores
    float* smf = (float*)dynsm;
    float* sqa = (float*)(dynsm + 66048);
    float* sqb = (float*)(dynsm + 66048 + 512);

    if (tid < 128) {
        sqa[tid] = g_sq[bi * 128 + tid];
        sqb[tid] = g_sq[bj * 128 + tid];
    }
    const int grp = lane >> 2, qc = (lane & 3) * 2;
    #pragma unroll
    for (int fm = 0; fm < 4; fm++) {
        const int m0 = wm + fm * 16 + grp;
        #pragma unroll
        for (int fn = 0; fn < 4; fn++) {
            const int n0 = wn + fn * 8 + qc;
            smf[m0 * 129 + n0]           = acc[fm][fn][0];
            smf[m0 * 129 + n0 + 1]       = acc[fm][fn][1];
            smf[(m0 + 8) * 129 + n0]     = acc[fm][fn][2];
            smf[(m0 + 8) * 129 + n0 + 1] = acc[fm][fn][3];
        }
    }
    __syncthreads();

    #pragma unroll
    for (int it = 0; it < 16; it++) {
        const int mr = it * 8 + wid;
        const float si = sqa[mr];
        ushort4 v;
        v.x = quant16(fmaf(-2.f, smf[mr * 129 + lane * 4 + 0], si + sqb[lane * 4 + 0]));
        v.y = quant16(fmaf(-2.f, smf[mr * 129 + lane * 4 + 1], si + sqb[lane * 4 + 1]));
        v.z = quant16(fmaf(-2.f, smf[mr * 129 + lane * 4 + 2], si + sqb[lane * 4 + 2]));
        v.w = quant16(fmaf(-2.f, smf[mr * 129 + lane * 4 + 3], si + sqb[lane * 4 + 3]));
        if (bi == bj) {
            if (mr == lane * 4 + 0) v.x = 65535;
            if (mr == lane * 4 + 1) v.y = 65535;
            if (mr == lane * 4 + 2) v.z = 65535;
            if (mr == lane * 4 + 3) v.w = 65535;
        }
        *(ushort4*)(g_pdq + (size_t)(bi * 128 + mr) * BB + bj * 128 + lane * 4) = v;
    }
    if (bi != bj) {
        #pragma unroll
        for (int it = 0; it < 16; it++) {
            const int nr = it * 8 + wid;
            const float sj = sqb[nr];
            ushort4 v;
            v.x = quant16(fmaf(-2.f, smf[(lane * 4 + 0) * 129 + nr], sqa[lane * 4 + 0] + sj));
            v.y = quant16(fmaf(-2.f, smf[(lane * 4 + 1) * 129 + nr], sqa[lane * 4 + 1] + sj));
            v.z = quant16(fmaf(-2.f, smf[(lane * 4 + 2) * 129 + nr], sqa[lane * 4 + 2] + sj));
            v.w = quant16(fmaf(-2.f, smf[(lane * 4 + 3) * 129 + nr], sqa[lane * 4 + 3] + sj));
            *(ushort4*)(g_pdq + (size_t)(bj * 128 + nr) * BB + bi * 128 + lane * 4) = v;
        }
    }
}

// ---------------- fused: hierarchical top-12 + exact refine + loss ----------------
// Phase 1: each warp selects top-12 of its 512 elements (shfl only, no barriers).
// Phase 2: warp 0 merges 96 -> 12.  Phase 3: exact fp32 refine + masked loss.
__global__ void __launch_bounds__(256) select_refine_kernel(
    const float* __restrict__ zi, const float* __restrict__ zj,
    const int* __restrict__ labels) {
    const int r    = blockIdx.x;
    const int tid  = threadIdx.x;
    const int lane = tid & 31;
    const int wid  = tid >> 5;
    const unsigned INFK = 0xFFFFFFFFu;

    __shared__ unsigned s_cand[8 * KSEL];      // 96 warp candidates
    __shared__ unsigned s_sel[KSEL];
    __shared__ unsigned long long s_key[KSEL];
    __shared__ float s_con[KSEL];
    __shared__ float s_rad;

    // ---- phase 1: warp-local top-12 of 512 ----
    const uint4* rowq = (const uint4*)(g_pdq + (size_t)r * BB);
    unsigned v[16];
    {
        const int base8 = wid * 64 + lane * 2;       // uint4 index (8 u16 each)
        uint4 p0 = rowq[base8];
        uint4 p1 = rowq[base8 + 1];
        const int jb = wid * 512 + lane * 16;
        v[0]  = ((p0.x & 0xFFFFu) << 12) | (jb + 0);
        v[1]  = ((p0.x >> 16) << 12)     | (jb + 1);
        v[2]  = ((p0.y & 0xFFFFu) << 12) | (jb + 2);
        v[3]  = ((p0.y >> 16) << 12)     | (jb + 3);
        v[4]  = ((p0.z & 0xFFFFu) << 12) | (jb + 4);
        v[5]  = ((p0.z >> 16) << 12)     | (jb + 5);
        v[6]  = ((p0.w & 0xFFFFu) << 12) | (jb + 6);
        v[7]  = ((p0.w >> 16) << 12)     | (jb + 7);
        v[8]  = ((p1.x & 0xFFFFu) << 12) | (jb + 8);
        v[9]  = ((p1.x >> 16) << 12)     | (jb + 9);
        v[10] = ((p1.y & 0xFFFFu) << 12) | (jb + 10);
        v[11] = ((p1.y >> 16) << 12)     | (jb + 11);
        v[12] = ((p1.z & 0xFFFFu) << 12) | (jb + 12);
        v[13] = ((p1.z >> 16) << 12)     | (jb + 13);
        v[14] = ((p1.w & 0xFFFFu) << 12) | (jb + 14);
        v[15] = ((p1.w >> 16) << 12)     | (jb + 15);
    }
    unsigned loc = v[0];
    #pragma unroll
    for (int k = 1; k < 16; k++) loc = min(loc, v[k]);

    #pragma unroll
    for (int sel = 0; sel < KSEL; sel++) {
        unsigned wmn = loc;
        #pragma unroll
        for (int o = 16; o > 0; o >>= 1)
            wmn = min(wmn, __shfl_xor_sync(0xffffffffu, wmn, o));
        if (lane == 0) s_cand[wid * KSEL + sel] = wmn;
        if (loc == wmn) {   // unique keys: exactly one owner pops
            loc = INFK;
            #pragma unroll
            for (int k = 0; k < 16; k++) {
                if (v[k] == wmn) v[k] = INFK;
                loc = min(loc, v[k]);
            }
        }
    }
    __syncthreads();

    // ---- phase 2: warp 0 merges 96 -> 12 ----
    if (wid == 0) {
        unsigned m0 = s_cand[lane];
        unsigned m1 = s_cand[lane + 32];
        unsigned m2 = s_cand[lane + 64];
        unsigned lmin = min(m0, min(m1, m2));
        #pragma unroll
        for (int sel = 0; sel < KSEL; sel++) {
            unsigned wmn = lmin;
            #pragma unroll
            for (int o = 16; o > 0; o >>= 1)
                wmn = min(wmn, __shfl_xor_sync(0xffffffffu, wmn, o));
            if (lane == 0) s_sel[sel] = wmn;
            if (lmin == wmn) {
                if (m0 == wmn) m0 = INFK;
                if (m1 == wmn) m1 = INFK;
                if (m2 == wmn) m2 = INFK;
                lmin = min(m0, min(m1, m2));
            }
        }
    }
    __syncthreads();

    // ---- phase 3: exact fp32 d2 for the 12 candidates ----
    const float* rowr = (r < NN) ? (zi + (size_t)r * DD) : (zj + (size_t)(r - NN) * DD);
    const float sqr = g_sq[r];

    #pragma unroll
    for (int t = wid; t < KSEL; t += 8) {
        const int j = (int)(s_sel[t] & 0xFFFu);
        const float* rowc = (j < NN) ? (zi + (size_t)j * DD)
                                     : (zj + (size_t)(j - NN) * DD);
        float s = 0.f;
        #pragma unroll
        for (int q = 0; q < 4; q++) {
            float4 a = *(const float4*)(rowr + (q * 32 + lane) * 4);
            float4 b = *(const float4*)(rowc + (q * 32 + lane) * 4);
            s += a.x * b.x + a.y * b.y + a.z * b.z + a.w * b.w;
        }
        #pragma unroll
        for (int o = 16; o > 0; o >>= 1)
            s += __shfl_down_sync(0xffffffffu, s, o);
        if (lane == 0) {
            const float d2 = fmaxf(fmaf(-2.f, s, sqr + g_sq[j]), 0.f);
            s_key[t] = ((unsigned long long)__float_as_uint(d2) << 32) | (unsigned)j;
        }
    }
    __syncthreads();

    // exact sort of 12 keys (lexicographic (d2, j))
    if (tid == 0) {
        #pragma unroll
        for (int a2 = 1; a2 < KSEL; a2++) {
            unsigned long long key = s_key[a2];
            int b2 = a2 - 1;
            while (b2 >= 0 && s_key[b2] > key) { s_key[b2 + 1] = s_key[b2]; b2--; }
            s_key[b2 + 1] = key;
        }
        s_rad = sqrtf(__uint_as_float((unsigned)(s_key[0] >> 32)));
    }
    __syncthreads();

    const float radius = s_rad;
    const int lr = labels[r & (NN - 1)];

    #pragma unroll
    for (int t = wid; t < TOPK; t += 8) {
        const unsigned long long key = s_key[t];
        const int   j  = (int)(key & 0xFFFFFFFFu);
        const float pd = sqrtf(__uint_as_float((unsigned)(key >> 32)));
        const float w  = 1.f - fminf(fmaxf((pd - radius) / radius, 0.f), 1.f);

        const int lj = labels[j & (NN - 1)];
        const bool msk = (lr == lj) && (lr != -1) && (lj != -1) &&
                         ((r & (NN - 1)) != (j & (NN - 1)));

        float4 pa = *(const float4*)(g_probs + (size_t)r * CC + lane * 4);
        float4 pb = *(const float4*)(g_probs + (size_t)j * CC + lane * 4);
        float s = pa.x * pb.x + pa.y * pb.y + pa.z * pb.z + pa.w * pb.w;
        #pragma unroll
        for (int o = 16; o > 0; o >>= 1)
            s += __shfl_down_sync(0xffffffffu, s, o);
        if (lane == 0) s_con[t] = msk ? (w * s) : 0.f;
    }
    __syncthreads();

    if (tid == 0) {
        float sum = 0.f;
        #pragma unroll
        for (int t = 0; t < TOPK; t++) sum += s_con[t];
        g_partial[r] = sum;
    }
}

// ---------------- deterministic final reduction ----------------
__global__ void __launch_bounds__(1024) finalize_kernel(float* __restrict__ out) {
    __shared__ float sm[1024];
    const int tid = threadIdx.x;
    float s = g_partial[tid] + g_partial[tid + 1024] +
              g_partial[tid + 2048] + g_partial[tid + 3072];
    sm[tid] = s;
    __syncthreads();
    for (int sfx = 512; sfx > 0; sfx >>= 1) {
        if (tid < sfx) sm[tid] += sm[tid + sfx];
        __syncthreads();
    }
    if (tid == 0) out[0] = sm[0] / (float)((size_t)BB * BB);
}

// ---------------- launch ----------------
extern "C" void kernel_launch(void* const* d_in, const int* in_sizes, int n_in,
                              void* d_out, int out_size) {
    const float* zi = (const float*)d_in[0];
    const float* zj = (const float*)d_in[1];
    const float* pi = (const float*)d_in[2];
    const float* pj = (const float*)d_in[3];
    const int*   pl = (const int*)d_in[4];
    float* out = (float*)d_out;

    static int cfg = 0;
    if (!cfg) {
        cudaFuncSetAttribute(dist_gemm_mma,
                             cudaFuncAttributeMaxDynamicSharedMemorySize, DSMEM_B);
        cfg = 1;
    }

    pack_kernel<<<1024, 256>>>(zi, zj, pi, pj);
    sqnorm_kernel<<<1024, 128>>>(zi, zj);
    dist_gemm_mma<<<528, 256, DSMEM_B>>>();
    select_refine_kernel<<<BB, 256>>>(zi, zj, pl);
    finalize_kernel<<<1, 1024>>>(out);
}

// round 10
// speedup vs baseline: 1.0848x; 1.0848x over previous
#include <cuda_runtime.h>
#include <cuda_bf16.h>
#include <stdint.h>

#define NN   2048
#define DD   512
#define CC   128
#define BB   4096
#define TOPK 10
#define KSEL 12

// ---------------- device scratch ----------------
__device__ __align__(16) __nv_bfloat16 g_hi[(size_t)BB * DD];   // 4 MB
__device__ __align__(16) unsigned short g_pdq[(size_t)BB * BB]; // 32 MB quantized d2
__device__ __align__(16) float g_probs[(size_t)BB * CC];
__device__ __align__(16) int   g_cand[(size_t)BB * KSEL];
__device__ float g_sq[BB];
__device__ float g_partial[BB];

// ---------------- helpers ----------------
__device__ __forceinline__ uint32_t smem_u32(const void* p) {
    uint32_t a;
    asm("{ .reg .u64 t; cvta.to.shared.u64 t, %1; cvt.u32.u64 %0, t; }"
        : "=r"(a) : "l"(p));
    return a;
}
__device__ __forceinline__ void ldsm4(uint32_t& r0, uint32_t& r1, uint32_t& r2,
                                      uint32_t& r3, uint32_t addr) {
    asm volatile("ldmatrix.sync.aligned.m8n8.x4.shared.b16 {%0,%1,%2,%3}, [%4];"
                 : "=r"(r0), "=r"(r1), "=r"(r2), "=r"(r3) : "r"(addr));
}
__device__ __forceinline__ void mma16816(float* c, const uint32_t* a,
                                         uint32_t b0, uint32_t b1) {
    asm volatile(
        "mma.sync.aligned.m16n8k16.row.col.f32.bf16.bf16.f32 "
        "{%0,%1,%2,%3}, {%4,%5,%6,%7}, {%8,%9}, {%0,%1,%2,%3};"
        : "+f"(c[0]), "+f"(c[1]), "+f"(c[2]), "+f"(c[3])
        : "r"(a[0]), "r"(a[1]), "r"(a[2]), "r"(a[3]), "r"(b0), "r"(b1));
}
#define CP_ASYNC16(dst, src) \
    asm volatile("cp.async.cg.shared.global [%0], [%1], 16;" :: "r"(dst), "l"(src))
#define CP_COMMIT()  asm volatile("cp.async.commit_group;" ::: "memory")
#define CP_WAIT0()   asm volatile("cp.async.wait_group 0;" ::: "memory")

__device__ __forceinline__ unsigned short quant16(float d2) {
    int q = (int)(d2 * 16.f);
    q = max(0, min(q, 65534));
    return (unsigned short)q;
}

// ---------------- fused pack (bf16 hi) + sqnorm + probs copy ----------------
// one warp per row: single read of zi/zj feeds both the bf16 store and sq-sum
__global__ void __launch_bounds__(256) pack_sq_kernel(
    const float* __restrict__ zi, const float* __restrict__ zj,
    const float* __restrict__ pi, const float* __restrict__ pj) {
    const int warp = (blockIdx.x * blockDim.x + threadIdx.x) >> 5;
    const int lane = threadIdx.x & 31;
    if (warp >= BB) return;
    const float* row = (warp < NN) ? (zi + (size_t)warp * DD)
                                   : (zj + (size_t)(warp - NN) * DD);
    float s = 0.f;
    #pragma unroll
    for (int q = 0; q < 4; q++) {
        const int e = (q * 32 + lane) * 4;
        float4 v = *(const float4*)(row + e);
        s += v.x * v.x + v.y * v.y + v.z * v.z + v.w * v.w;
        __nv_bfloat162 h0{__float2bfloat16(v.x), __float2bfloat16(v.y)};
        __nv_bfloat162 h1{__float2bfloat16(v.z), __float2bfloat16(v.w)};
        uint2 pk{*(const unsigned*)&h0, *(const unsigned*)&h1};
        *(uint2*)(g_hi + (size_t)warp * DD + e) = pk;
    }
    #pragma unroll
    for (int off = 16; off > 0; off >>= 1)
        s += __shfl_down_sync(0xffffffffu, s, off);
    if (lane == 0) g_sq[warp] = s;

    // probs: one float4 per lane covers the 128-wide row
    const float* prow = (warp < NN) ? (pi + (size_t)warp * CC)
                                    : (pj + (size_t)(warp - NN) * CC);
    *(float4*)(g_probs + (size_t)warp * CC + lane * 4) =
        *(const float4*)(prow + lane * 4);
}

// ---------------- 1-product bf16 GEMM -> quantized d2 ----------------
#define BUF_B   10240
#define STAGE_B (2 * BUF_B)
#define DSMEM_B 67072

extern __shared__ char dynsm[];

__global__ void __launch_bounds__(256, 1) dist_gemm_mma() {
    int t = blockIdx.x;
    int bi = 0;
    while (t >= 32 - bi) { t -= 32 - bi; bi++; }
    const int bj = bi + t;

    const int tid  = threadIdx.x;
    const int wid  = tid >> 5;
    const int lane = tid & 31;
    const int wm   = (wid >> 2) * 64;
    const int wn   = (wid & 3) * 32;

    const uint32_t sbase = smem_u32(dynsm);

    const __nv_bfloat16* src[4];
    uint32_t dst[4];
    #pragma unroll
    for (int it = 0; it < 4; it++) {
        const int cid = it * 256 + tid;
        const int b   = cid >> 9;
        const int w   = cid & 511;
        const int row = w >> 2;
        const int seg = w & 3;
        const int grow = ((b == 0) ? bi : bj) * 128 + row;
        src[it] = g_hi + (size_t)grow * DD + seg * 8;
        dst[it] = sbase + b * BUF_B + row * 80 + seg * 16;
    }

    float acc[4][4][4];
    #pragma unroll
    for (int fm = 0; fm < 4; fm++)
        #pragma unroll
        for (int fn = 0; fn < 4; fn++)
            #pragma unroll
            for (int e = 0; e < 4; e++) acc[fm][fn][e] = 0.f;

    #pragma unroll
    for (int it = 0; it < 4; it++) CP_ASYNC16(dst[it], src[it]);
    CP_COMMIT();

    for (int ch = 0; ch < 16; ch++) {
        CP_WAIT0();
        __syncthreads();
        if (ch < 15) {
            const uint32_t soff = ((ch + 1) & 1) * STAGE_B;
            #pragma unroll
            for (int it = 0; it < 4; it++)
                CP_ASYNC16(dst[it] + soff, src[it] + (ch + 1) * 32);
            CP_COMMIT();
        }
        const uint32_t stg = sbase + (ch & 1) * STAGE_B;

        #pragma unroll
        for (int kst = 0; kst < 2; kst++) {
            const uint32_t ko = kst * 32 + (lane >> 4) * 16;
            uint32_t ahi[4][4];
            #pragma unroll
            for (int fm = 0; fm < 4; fm++) {
                const uint32_t ra = (wm + fm * 16 + (lane & 15)) * 80 + ko;
                ldsm4(ahi[fm][0], ahi[fm][1], ahi[fm][2], ahi[fm][3], stg + ra);
            }
            uint32_t bh[2][4];
            #pragma unroll
            for (int fp = 0; fp < 2; fp++) {
                const uint32_t rb = (wn + fp * 16 + (lane & 15)) * 80 + ko;
                ldsm4(bh[fp][0], bh[fp][1], bh[fp][2], bh[fp][3],
                      stg + BUF_B + rb);
            }
            #pragma unroll
            for (int fm = 0; fm < 4; fm++)
                #pragma unroll
                for (int fn = 0; fn < 4; fn++) {
                    const int fp = fn >> 1, s = fn & 1;
                    mma16816(acc[fm][fn], ahi[fm], bh[fp][s], bh[fp][s + 2]);
                }
        }
        __syncthreads();
    }

    // epilogue: dots -> smem -> quantized d2 stores
    float* smf = (float*)dynsm;
    float* sqa = (float*)(dynsm + 66048);
    float* sqb = (float*)(dynsm + 66048 + 512);

    if (tid < 128) {
        sqa[tid] = g_sq[bi * 128 + tid];
        sqb[tid] = g_sq[bj * 128 + tid];
    }
    const int grp = lane >> 2, qc = (lane & 3) * 2;
    #pragma unroll
    for (int fm = 0; fm < 4; fm++) {
        const int m0 = wm + fm * 16 + grp;
        #pragma unroll
        for (int fn = 0; fn < 4; fn++) {
            const int n0 = wn + fn * 8 + qc;
            smf[m0 * 129 + n0]           = acc[fm][fn][0];
            smf[m0 * 129 + n0 + 1]       = acc[fm][fn][1];
            smf[(m0 + 8) * 129 + n0]     = acc[fm][fn][2];
            smf[(m0 + 8) * 129 + n0 + 1] = acc[fm][fn][3];
        }
    }
    __syncthreads();

    #pragma unroll
    for (int it = 0; it < 16; it++) {
        const int mr = it * 8 + wid;
        const float si = sqa[mr];
        ushort4 v;
        v.x = quant16(fmaf(-2.f, smf[mr * 129 + lane * 4 + 0], si + sqb[lane * 4 + 0]));
        v.y = quant16(fmaf(-2.f, smf[mr * 129 + lane * 4 + 1], si + sqb[lane * 4 + 1]));
        v.z = quant16(fmaf(-2.f, smf[mr * 129 + lane * 4 + 2], si + sqb[lane * 4 + 2]));
        v.w = quant16(fmaf(-2.f, smf[mr * 129 + lane * 4 + 3], si + sqb[lane * 4 + 3]));
        if (bi == bj) {
            if (mr == lane * 4 + 0) v.x = 65535;
            if (mr == lane * 4 + 1) v.y = 65535;
            if (mr == lane * 4 + 2) v.z = 65535;
            if (mr == lane * 4 + 3) v.w = 65535;
        }
        *(ushort4*)(g_pdq + (size_t)(bi * 128 + mr) * BB + bj * 128 + lane * 4) = v;
    }
    if (bi != bj) {
        #pragma unroll
        for (int it = 0; it < 16; it++) {
            const int nr = it * 8 + wid;
            const float sj = sqb[nr];
            ushort4 v;
            v.x = quant16(fmaf(-2.f, smf[(lane * 4 + 0) * 129 + nr], sqa[lane * 4 + 0] + sj));
            v.y = quant16(fmaf(-2.f, smf[(lane * 4 + 1) * 129 + nr], sqa[lane * 4 + 1] + sj));
            v.z = quant16(fmaf(-2.f, smf[(lane * 4 + 2) * 129 + nr], sqa[lane * 4 + 2] + sj));
            v.w = quant16(fmaf(-2.f, smf[(lane * 4 + 3) * 129 + nr], sqa[lane * 4 + 3] + sj));
            *(ushort4*)(g_pdq + (size_t)(bj * 128 + nr) * BB + bi * 128 + lane * 4) = v;
        }
    }
}

// ---------------- approx top-12 per row: ONE barrier per round ----------------
__global__ void __launch_bounds__(256) topk12_kernel() {
    const int r    = blockIdx.x;
    const int tid  = threadIdx.x;
    const int lane = tid & 31;
    const int wid  = tid >> 5;
    const unsigned INFK = 0xFFFFFFFFu;

    __shared__ unsigned swm[2][8];     // parity double-buffered warp minima
    __shared__ unsigned s_win[KSEL];

    const uint4* rowq = (const uint4*)(g_pdq + (size_t)r * BB);

    unsigned v[16];
    #pragma unroll
    for (int h = 0; h < 2; h++) {
        uint4 p = rowq[tid * 2 + h];
        const unsigned w0 = p.x, w1 = p.y, w2 = p.z, w3 = p.w;
        const int jb = tid * 16 + h * 8;
        v[h * 8 + 0] = ((w0 & 0xFFFFu) << 12) | (jb + 0);
        v[h * 8 + 1] = ((w0 >> 16) << 12)     | (jb + 1);
        v[h * 8 + 2] = ((w1 & 0xFFFFu) << 12) | (jb + 2);
        v[h * 8 + 3] = ((w1 >> 16) << 12)     | (jb + 3);
        v[h * 8 + 4] = ((w2 & 0xFFFFu) << 12) | (jb + 4);
        v[h * 8 + 5] = ((w2 >> 16) << 12)     | (jb + 5);
        v[h * 8 + 6] = ((w3 & 0xFFFFu) << 12) | (jb + 6);
        v[h * 8 + 7] = ((w3 >> 16) << 12)     | (jb + 7);
    }

    unsigned loc = v[0];
    #pragma unroll
    for (int k = 1; k < 16; k++) loc = min(loc, v[k]);

    // 12 rounds, ONE __syncthreads each: the parity buffer separates
    // round s+1's writes of buffer p' from round s-1's reads of p'.
    #pragma unroll
    for (int sel = 0; sel < KSEL; sel++) {
        const int p = sel & 1;
        unsigned wmn = loc;
        #pragma unroll
        for (int o = 16; o > 0; o >>= 1)
            wmn = min(wmn, __shfl_xor_sync(0xffffffffu, wmn, o));
        if (lane == 0) swm[p][wid] = wmn;
        __syncthreads();
        unsigned win = swm[p][0];
        #pragma unroll
        for (int i = 1; i < 8; i++) win = min(win, swm[p][i]);
        if (tid == 0) s_win[sel] = win;
        if (loc == win) {   // unique key: exactly one owner pops
            loc = INFK;
            #pragma unroll
            for (int k = 0; k < 16; k++) {
                if (v[k] == win) v[k] = INFK;
                loc = min(loc, v[k]);
            }
        }
    }
    __syncthreads();

    if (tid < KSEL) g_cand[(size_t)r * KSEL + tid] = (int)(s_win[tid] & 0xFFFu);
}

// ---------------- exact refine of 12 candidates + masked loss ----------------
__global__ void __launch_bounds__(128) refine_loss_kernel(
    const float* __restrict__ zi, const float* __restrict__ zj,
    const int* __restrict__ labels) {
    const int r    = blockIdx.x;
    const int tid  = threadIdx.x;
    const int lane = tid & 31;
    const int wid  = tid >> 5;

    __shared__ int s_j[KSEL];
    __shared__ unsigned long long s_key[KSEL];
    __shared__ float s_con[TOPK];
    __shared__ float s_rad;

    if (tid < KSEL) s_j[tid] = g_cand[(size_t)r * KSEL + tid];
    if (tid < TOPK) s_con[tid] = 0.f;
    __syncthreads();

    const float* rowr = (r < NN) ? (zi + (size_t)r * DD) : (zj + (size_t)(r - NN) * DD);
    const float sqr = g_sq[r];

    for (int t = wid; t < KSEL; t += 4) {
        const int j = s_j[t];
        const float* rowc = (j < NN) ? (zi + (size_t)j * DD)
                                     : (zj + (size_t)(j - NN) * DD);
        float s = 0.f;
        #pragma unroll
        for (int q = 0; q < 4; q++) {
            float4 a = *(const float4*)(rowr + (q * 32 + lane) * 4);
            float4 b = *(const float4*)(rowc + (q * 32 + lane) * 4);
            s += a.x * b.x + a.y * b.y + a.z * b.z + a.w * b.w;
        }
        #pragma unroll
        for (int o = 16; o > 0; o >>= 1)
            s += __shfl_down_sync(0xffffffffu, s, o);
        if (lane == 0) {
            const float d2 = fmaxf(fmaf(-2.f, s, sqr + g_sq[j]), 0.f);
            s_key[t] = ((unsigned long long)__float_as_uint(d2) << 32) | (unsigned)j;
        }
    }
    __syncthreads();

    if (tid == 0) {
        #pragma unroll
        for (int a2 = 1; a2 < KSEL; a2++) {
            unsigned long long key = s_key[a2];
            int b2 = a2 - 1;
            while (b2 >= 0 && s_key[b2] > key) { s_key[b2 + 1] = s_key[b2]; b2--; }
            s_key[b2 + 1] = key;
        }
        s_rad = sqrtf(__uint_as_float((unsigned)(s_key[0] >> 32)));
    }
    __syncthreads();

    const float radius = s_rad;
    const int lr = labels[r & (NN - 1)];

    for (int t = wid; t < TOPK; t += 4) {
        const unsigned long long key = s_key[t];
        const int   j  = (int)(key & 0xFFFFFFFFu);
        const float pd = sqrtf(__uint_as_float((unsigned)(key >> 32)));
        const float w  = 1.f - fminf(fmaxf((pd - radius) / radius, 0.f), 1.f);

        const int lj = labels[j & (NN - 1)];
        const bool msk = (lr == lj) && (lr != -1) && (lj != -1) &&
                         ((r & (NN - 1)) != (j & (NN - 1)));

        float4 pa = *(const float4*)(g_probs + (size_t)r * CC + lane * 4);
        float4 pb = *(const float4*)(g_probs + (size_t)j * CC + lane * 4);
        float s = pa.x * pb.x + pa.y * pb.y + pa.z * pb.z + pa.w * pb.w;
        #pragma unroll
        for (int o = 16; o > 0; o >>= 1)
            s += __shfl_down_sync(0xffffffffu, s, o);
        if (lane == 0) s_con[t] = msk ? (w * s) : 0.f;
    }
    __syncthreads();

    if (tid == 0) {
        float sum = 0.f;
        #pragma unroll
        for (int t = 0; t < TOPK; t++) sum += s_con[t];
        g_partial[r] = sum;
    }
}

// ---------------- deterministic final reduction ----------------
__global__ void __launch_bounds__(1024) finalize_kernel(float* __restrict__ out) {
    __shared__ float sm[1024];
    const int tid = threadIdx.x;
    float s = g_partial[tid] + g_partial[tid + 1024] +
              g_partial[tid + 2048] + g_partial[tid + 3072];
    sm[tid] = s;
    __syncthreads();
    for (int sfx = 512; sfx > 0; sfx >>= 1) {
        if (tid < sfx) sm[tid] += sm[tid + sfx];
        __syncthreads();
    }
    if (tid == 0) out[0] = sm[0] / (float)((size_t)BB * BB);
}

// ---------------- launch ----------------
extern "C" void kernel_launch(void* const* d_in, const int* in_sizes, int n_in,
                              void* d_out, int out_size) {
    const float* zi = (const float*)d_in[0];
    const float* zj = (const float*)d_in[1];
    const float* pi = (const float*)d_in[2];
    const float* pj = (const float*)d_in[3];
    const int*   pl = (const int*)d_in[4];
    float* out = (float*)d_out;

    static int cfg = 0;
    if (!cfg) {
        cudaFuncSetAttribute(dist_gemm_mma,
                             cudaFuncAttributeMaxDynamicSharedMemorySize, DSMEM_B);
        cfg = 1;
    }

    pack_sq_kernel<<<512, 256>>>(zi, zj, pi, pj);
    dist_gemm_mma<<<528, 256, DSMEM_B>>>();
    topk12_kernel<<<BB, 256>>>();
    refine_loss_kernel<<<BB, 128>>>(zi, zj, pl);
    finalize_kernel<<<1, 1024>>>(out);
}